// round 15
// baseline (speedup 1.0000x reference)
#include <cuda_runtime.h>
#include <cuda_bf16.h>
#include <mma.h>
#include <math.h>
#include <cstdint>

using namespace nvcuda;

#define B_    4
#define T_    2048
#define C_    2048
#define H_    16
#define KVH_  4
#define D_    128

// ---------------------------------------------------------------------------
// Scratch (device globals — no allocation allowed)
// ---------------------------------------------------------------------------
__device__ __nv_bfloat16 g_xh [B_ * T_ * C_];
__device__ __nv_bfloat16 g_xl [B_ * T_ * C_];
__device__ __nv_bfloat16 g_wqh[C_ * C_];
__device__ __nv_bfloat16 g_wql[C_ * C_];
__device__ __nv_bfloat16 g_wkh[KVH_ * D_ * C_];
__device__ __nv_bfloat16 g_wkl[KVH_ * D_ * C_];
__device__ __nv_bfloat16 g_wvh[KVH_ * D_ * C_];
__device__ __nv_bfloat16 g_wvl[KVH_ * D_ * C_];
__device__ __nv_bfloat16 g_woh[C_ * C_];
__device__ __nv_bfloat16 g_wol[C_ * C_];
__device__ __nv_bfloat16 g_ah [B_ * T_ * C_];   // flash O hi
__device__ __nv_bfloat16 g_al [B_ * T_ * C_];   // flash O lo
__device__ __nv_bfloat16 g_qh [B_ * T_ * H_   * D_];
__device__ __nv_bfloat16 g_ql [B_ * T_ * H_   * D_];
__device__ __nv_bfloat16 g_kh [B_ * T_ * KVH_ * D_];
__device__ __nv_bfloat16 g_kl [B_ * T_ * KVH_ * D_];
__device__ __nv_bfloat16 g_vh [B_ * T_ * KVH_ * D_];
__device__ __nv_bfloat16 g_vl [B_ * T_ * KVH_ * D_];

__device__ __forceinline__ uint32_t smem_u32(const void* p) {
    uint32_t a;
    asm("{ .reg .u64 t; cvta.to.shared.u64 t, %1; cvt.u32.u64 %0, t; }"
        : "=r"(a) : "l"(p));
    return a;
}
__device__ __forceinline__ void cp16(uint32_t saddr, const void* g) {
    asm volatile("cp.async.cg.shared.global [%0], [%1], 16;"
                 :: "r"(saddr), "l"(g) : "memory");
}
__device__ __forceinline__ void split1(float v, __nv_bfloat16& h, __nv_bfloat16& l) {
    h = __float2bfloat16(v);
    l = __float2bfloat16(v - __bfloat162float(h));
}

// FMA-pipe exp (avoids MUFU.EX2). x <= 0 here (s - rowmax).
// R15 FIX: clamp y BEFORE range decomposition. R14 clamped only n, leaving
// t = (y - n) astronomically large for the -1e30 init sentinel -> poly blew
// up to inf -> NaN. Now y>=-127 guarantees t in [-0.35, 0.35], and n=-127
// builds zero exponent bits -> returns exactly 0 for exp(-huge).
__device__ __forceinline__ float fast_exp(float x) {
    float y = fmaf(x, 1.4426950408889634f, 0.0f);
    y = fmaxf(y, -127.0f);
    const float n = rintf(y);
    const float t = (y - n) * 0.6931471805599453f;    // in [-0.347, 0.347]
    float e = fmaf(t, 0.00833333333f, 0.0416666667f);
    e = fmaf(t, e, 0.16666666667f);
    e = fmaf(t, e, 0.5f);
    e = fmaf(t, e, 1.0f);
    e = fmaf(t, e, 1.0f);
    const float sc = __int_as_float(((int)n + 127) << 23);   // 2^n (0 at n=-127)
    return e * sc;
}

// ---------------------------------------------------------------------------
// One-launch fp32 -> bf16 hi/lo split for x, Wq, Wk, Wv, Wo (range dispatch).
// ---------------------------------------------------------------------------
#define NX_  (B_ * T_ * C_)
#define NWQ_ (C_ * C_)
#define NWK_ (KVH_ * D_ * C_)
#define NALL_ (NX_ + 2 * NWQ_ + 2 * NWK_)

__global__ void split_all(
    const float* __restrict__ x,  __nv_bfloat16* __restrict__ xh,  __nv_bfloat16* __restrict__ xl,
    const float* __restrict__ wq, __nv_bfloat16* __restrict__ wqh, __nv_bfloat16* __restrict__ wql,
    const float* __restrict__ wk, __nv_bfloat16* __restrict__ wkh, __nv_bfloat16* __restrict__ wkl,
    const float* __restrict__ wv, __nv_bfloat16* __restrict__ wvh, __nv_bfloat16* __restrict__ wvl,
    const float* __restrict__ wo, __nv_bfloat16* __restrict__ woh, __nv_bfloat16* __restrict__ wol)
{
    long i = (long)blockIdx.x * blockDim.x + threadIdx.x;
    const float* s; __nv_bfloat16 *dh, *dl;
    if (i < NX_)                    { s = x;  dh = xh;  dl = xl; }
    else if ((i -= NX_)  < NWQ_)    { s = wq; dh = wqh; dl = wql; }
    else if ((i -= NWQ_) < NWK_)    { s = wk; dh = wkh; dl = wkl; }
    else if ((i -= NWK_) < NWK_)    { s = wv; dh = wvh; dl = wvl; }
    else if ((i -= NWK_) < NWQ_)    { s = wo; dh = woh; dl = wol; }
    else return;
    const float v = s[i];
    split1(v, dh[i], dl[i]);
}

// ---------------------------------------------------------------------------
// Shared GEMM config (R11-proven).
// ---------------------------------------------------------------------------
#define LDB        40
#define ARR_STRIDE (128 * LDB * 2)
#define STG_STRIDE (4 * ARR_STRIDE)
#define CS_LD      132
#define GEMM_SMEM  (2 * STG_STRIDE)

// ---------------------------------------------------------------------------
// Fused QKV GEMM + RoPE + scale + bf16 split (R13, unchanged).
// ---------------------------------------------------------------------------
__global__ __launch_bounds__(256) void gemm_qkv(
    const __nv_bfloat16* __restrict__ xh,  const __nv_bfloat16* __restrict__ xl,
    const __nv_bfloat16* __restrict__ wqh, const __nv_bfloat16* __restrict__ wql,
    const __nv_bfloat16* __restrict__ wkh, const __nv_bfloat16* __restrict__ wkl,
    const __nv_bfloat16* __restrict__ wvh, const __nv_bfloat16* __restrict__ wvl,
    const float* __restrict__ inv,
    __nv_bfloat16* __restrict__ qh, __nv_bfloat16* __restrict__ ql,
    __nv_bfloat16* __restrict__ kh, __nv_bfloat16* __restrict__ kl,
    __nv_bfloat16* __restrict__ vh, __nv_bfloat16* __restrict__ vl)
{
    extern __shared__ char sm8[];
    const uint32_t sb = smem_u32(sm8);
    const int tid   = threadIdx.x;
    const int warp  = tid >> 5;
    const int warpM = warp >> 2;
    const int warpN = warp & 3;
    const int bm    = blockIdx.y * 128;
    const int bx    = blockIdx.x;
    const int K     = C_;

    const __nv_bfloat16 *Bh, *Bl;
    __nv_bfloat16 *dh, *dl;
    int bn, mode, nseg;
    if (bx < 16)      { Bh = wqh; Bl = wql; bn = bx * 128;        mode = 1; nseg = 2048; dh = qh; dl = ql; }
    else if (bx < 20) { Bh = wkh; Bl = wkl; bn = (bx - 16) * 128; mode = 2; nseg = 512;  dh = kh; dl = kl; }
    else              { Bh = wvh; Bl = wvl; bn = (bx - 20) * 128; mode = 3; nseg = 512;  dh = vh; dl = vl; }

    wmma::fragment<wmma::accumulator, 16, 16, 16, float> acc[4][2];
#pragma unroll
    for (int i = 0; i < 4; i++)
#pragma unroll
        for (int j = 0; j < 2; j++) wmma::fill_fragment(acc[i][j], 0.0f);

    auto stage_load = [&](int k0, int stg) {
#pragma unroll
        for (int t = 0; t < 2; t++) {
            const int idx = tid + t * 256;
            const int r   = idx >> 2;
            const int c8  = (idx & 3) << 3;
            const size_t ga = (size_t)(bm + r) * K + k0 + c8;
            const size_t gb = (size_t)(bn + r) * K + k0 + c8;
            const uint32_t so = sb + stg * STG_STRIDE + r * (LDB * 2) + c8 * 2;
            cp16(so,                  xh + ga);
            cp16(so + ARR_STRIDE,     xl + ga);
            cp16(so + 2 * ARR_STRIDE, Bh + gb);
            cp16(so + 3 * ARR_STRIDE, Bl + gb);
        }
        asm volatile("cp.async.commit_group;" ::: "memory");
    };

    stage_load(0, 0);

    for (int k0 = 0; k0 < K; k0 += 32) {
        const int stg = (k0 >> 5) & 1;
        if (k0 + 32 < K) {
            stage_load(k0 + 32, stg ^ 1);
            asm volatile("cp.async.wait_group 1;" ::: "memory");
        } else {
            asm volatile("cp.async.wait_group 0;" ::: "memory");
        }
        __syncthreads();

        const __nv_bfloat16* Ahs = (const __nv_bfloat16*)(sm8 + stg * STG_STRIDE);
        const __nv_bfloat16* Als = (const __nv_bfloat16*)(sm8 + stg * STG_STRIDE + ARR_STRIDE);
        const __nv_bfloat16* Bhs = (const __nv_bfloat16*)(sm8 + stg * STG_STRIDE + 2 * ARR_STRIDE);
        const __nv_bfloat16* Bls = (const __nv_bfloat16*)(sm8 + stg * STG_STRIDE + 3 * ARR_STRIDE);

#pragma unroll
        for (int ks = 0; ks < 2; ks++) {
            wmma::fragment<wmma::matrix_b, 16, 16, 16, __nv_bfloat16,
                           wmma::col_major> fbh[2], fbl[2];
#pragma unroll
            for (int j = 0; j < 2; j++) {
                wmma::load_matrix_sync(fbh[j], Bhs + (warpN * 32 + j * 16) * LDB + ks * 16, LDB);
                wmma::load_matrix_sync(fbl[j], Bls + (warpN * 32 + j * 16) * LDB + ks * 16, LDB);
            }
#pragma unroll
            for (int i = 0; i < 4; i++) {
                wmma::fragment<wmma::matrix_a, 16, 16, 16, __nv_bfloat16,
                               wmma::row_major> fah, fal;
                wmma::load_matrix_sync(fah, Ahs + (warpM * 64 + i * 16) * LDB + ks * 16, LDB);
                wmma::load_matrix_sync(fal, Als + (warpM * 64 + i * 16) * LDB + ks * 16, LDB);
#pragma unroll
                for (int j = 0; j < 2; j++) {
                    wmma::mma_sync(acc[i][j], fah, fbh[j], acc[i][j]);
                    wmma::mma_sync(acc[i][j], fah, fbl[j], acc[i][j]);
                    wmma::mma_sync(acc[i][j], fal, fbh[j], acc[i][j]);
                }
            }
        }
        __syncthreads();
    }

    float* Cs = (float*)sm8;
#pragma unroll
    for (int i = 0; i < 4; i++)
#pragma unroll
        for (int j = 0; j < 2; j++)
            wmma::store_matrix_sync(&Cs[(warpM * 64 + i * 16) * CS_LD + warpN * 32 + j * 16],
                                    acc[i][j], CS_LD, wmma::mem_row_major);
    __syncthreads();

    const float rscale = 0.08838834764831845f;
#pragma unroll
    for (int it = 0; it < 16; it++) {
        const int idx = tid + it * 256;
        const int r   = idx >> 5;
        const int c4  = (idx & 31) << 2;
        float4 v = *(float4*)&Cs[r * CS_LD + c4];

        const int m   = bm + r;
        const int t   = m & (T_ - 1);
        const int col = bn + c4;
        const int d   = col & 127;

        if (mode != 3) {
            float s0, c0, s1, c1;
            sincosf(inv[(size_t)t * D_ + d],     &s0, &c0);
            sincosf(inv[(size_t)t * D_ + d + 2], &s1, &c1);
            float y0 = v.x * c0 - v.y * s0;
            float y1 = v.y * c0 + v.x * s0;
            float y2 = v.z * c1 - v.w * s1;
            float y3 = v.w * c1 + v.z * s1;
            if (mode == 1) { y0 *= rscale; y1 *= rscale; y2 *= rscale; y3 *= rscale; }
            v.x = y0; v.y = y1; v.z = y2; v.w = y3;
        }

        __nv_bfloat16 h0, h1, h2, h3, l0, l1, l2, l3;
        split1(v.x, h0, l0); split1(v.y, h1, l1);
        split1(v.z, h2, l2); split1(v.w, h3, l3);

        uint2 PH, PL;
        PH.x = (uint32_t)__bfloat16_as_ushort(h0) | ((uint32_t)__bfloat16_as_ushort(h1) << 16);
        PH.y = (uint32_t)__bfloat16_as_ushort(h2) | ((uint32_t)__bfloat16_as_ushort(h3) << 16);
        PL.x = (uint32_t)__bfloat16_as_ushort(l0) | ((uint32_t)__bfloat16_as_ushort(l1) << 16);
        PL.y = (uint32_t)__bfloat16_as_ushort(l2) | ((uint32_t)__bfloat16_as_ushort(l3) << 16);
        const size_t g = (size_t)m * nseg + col;
        *(uint2*)(dh + g) = PH;
        *(uint2*)(dl + g) = PL;
    }
}

// ---------------------------------------------------------------------------
// Output GEMM (R11, unchanged).
// ---------------------------------------------------------------------------
__global__ __launch_bounds__(256) void gemm_bf16s(
    const __nv_bfloat16* __restrict__ Ah, const __nv_bfloat16* __restrict__ Al,
    const __nv_bfloat16* __restrict__ Bh, const __nv_bfloat16* __restrict__ Bl,
    const float* __restrict__ bias, float* __restrict__ C,
    int M, int N, int K)
{
    extern __shared__ char sm8[];
    const uint32_t sb = smem_u32(sm8);
    const int tid   = threadIdx.x;
    const int warp  = tid >> 5;
    const int warpM = warp >> 2;
    const int warpN = warp & 3;
    const int bm    = blockIdx.y * 128;
    const int bn    = blockIdx.x * 128;

    wmma::fragment<wmma::accumulator, 16, 16, 16, float> acc[4][2];
#pragma unroll
    for (int i = 0; i < 4; i++)
#pragma unroll
        for (int j = 0; j < 2; j++) wmma::fill_fragment(acc[i][j], 0.0f);

    auto stage_load = [&](int k0, int stg) {
#pragma unroll
        for (int t = 0; t < 2; t++) {
            const int idx = tid + t * 256;
            const int r   = idx >> 2;
            const int c8  = (idx & 3) << 3;
            const size_t ga = (size_t)(bm + r) * K + k0 + c8;
            const size_t gb = (size_t)(bn + r) * K + k0 + c8;
            const uint32_t so = sb + stg * STG_STRIDE + r * (LDB * 2) + c8 * 2;
            cp16(so,                  Ah + ga);
            cp16(so + ARR_STRIDE,     Al + ga);
            cp16(so + 2 * ARR_STRIDE, Bh + gb);
            cp16(so + 3 * ARR_STRIDE, Bl + gb);
        }
        asm volatile("cp.async.commit_group;" ::: "memory");
    };

    stage_load(0, 0);

    for (int k0 = 0; k0 < K; k0 += 32) {
        const int stg = (k0 >> 5) & 1;
        if (k0 + 32 < K) {
            stage_load(k0 + 32, stg ^ 1);
            asm volatile("cp.async.wait_group 1;" ::: "memory");
        } else {
            asm volatile("cp.async.wait_group 0;" ::: "memory");
        }
        __syncthreads();

        const __nv_bfloat16* Ahs = (const __nv_bfloat16*)(sm8 + stg * STG_STRIDE);
        const __nv_bfloat16* Als = (const __nv_bfloat16*)(sm8 + stg * STG_STRIDE + ARR_STRIDE);
        const __nv_bfloat16* Bhs = (const __nv_bfloat16*)(sm8 + stg * STG_STRIDE + 2 * ARR_STRIDE);
        const __nv_bfloat16* Bls = (const __nv_bfloat16*)(sm8 + stg * STG_STRIDE + 3 * ARR_STRIDE);

#pragma unroll
        for (int ks = 0; ks < 2; ks++) {
            wmma::fragment<wmma::matrix_b, 16, 16, 16, __nv_bfloat16,
                           wmma::col_major> fbh[2], fbl[2];
#pragma unroll
            for (int j = 0; j < 2; j++) {
                wmma::load_matrix_sync(fbh[j], Bhs + (warpN * 32 + j * 16) * LDB + ks * 16, LDB);
                wmma::load_matrix_sync(fbl[j], Bls + (warpN * 32 + j * 16) * LDB + ks * 16, LDB);
            }
#pragma unroll
            for (int i = 0; i < 4; i++) {
                wmma::fragment<wmma::matrix_a, 16, 16, 16, __nv_bfloat16,
                               wmma::row_major> fah, fal;
                wmma::load_matrix_sync(fah, Ahs + (warpM * 64 + i * 16) * LDB + ks * 16, LDB);
                wmma::load_matrix_sync(fal, Als + (warpM * 64 + i * 16) * LDB + ks * 16, LDB);
#pragma unroll
                for (int j = 0; j < 2; j++) {
                    wmma::mma_sync(acc[i][j], fah, fbh[j], acc[i][j]);
                    wmma::mma_sync(acc[i][j], fah, fbl[j], acc[i][j]);
                    wmma::mma_sync(acc[i][j], fal, fbh[j], acc[i][j]);
                }
            }
        }
        __syncthreads();
    }

    float* Cs = (float*)sm8;
#pragma unroll
    for (int i = 0; i < 4; i++)
#pragma unroll
        for (int j = 0; j < 2; j++)
            wmma::store_matrix_sync(&Cs[(warpM * 64 + i * 16) * CS_LD + warpN * 32 + j * 16],
                                    acc[i][j], CS_LD, wmma::mem_row_major);
    __syncthreads();

#pragma unroll
    for (int it = 0; it < 16; it++) {
        const int idx = tid + it * 256;
        const int r   = idx >> 5;
        const int c4  = (idx & 31) << 2;
        float4 v = *(float4*)&Cs[r * CS_LD + c4];
        const float4 b = *(const float4*)(bias + bn + c4);
        v.x += b.x; v.y += b.y; v.z += b.z; v.w += b.w;
        *(float4*)(C + (size_t)(bm + r) * N + bn + c4) = v;
    }
}

// ---------------------------------------------------------------------------
// Tensor-core causal flash attention (R13 + fixed FMA-pipe fast_exp).
// ---------------------------------------------------------------------------
#define FQ_LD 136
#define FS_LD 68
#define FP_LD 72
#define FO_LD 132
#define F_QH 0
#define F_QL (F_QH + 64 * FQ_LD * 2)
#define F_KH (F_QL + 64 * FQ_LD * 2)
#define F_KL (F_KH + 64 * FQ_LD * 2)
#define F_VH (F_KL + 64 * FQ_LD * 2)
#define F_VL (F_VH + 64 * FQ_LD * 2)
#define F_PS (F_VL + 64 * FQ_LD * 2)
#define F_PH (F_PS + 64 * FS_LD * 4)
#define F_PL (F_PH + 64 * FP_LD * 2)
#define F_OS (F_PL + 64 * FP_LD * 2)
#define F_ST (F_OS + 64 * FO_LD * 4)
#define FLASH_SMEM (F_ST + 3 * 64 * 4)

__global__ __launch_bounds__(256) void flash_tc(
    const __nv_bfloat16* __restrict__ qh, const __nv_bfloat16* __restrict__ ql,
    const __nv_bfloat16* __restrict__ kh, const __nv_bfloat16* __restrict__ kl,
    const __nv_bfloat16* __restrict__ vh, const __nv_bfloat16* __restrict__ vl,
    __nv_bfloat16* __restrict__ oh_out, __nv_bfloat16* __restrict__ ol_out)
{
    extern __shared__ char smx[];
    __nv_bfloat16* QH = (__nv_bfloat16*)(smx + F_QH);
    __nv_bfloat16* QL = (__nv_bfloat16*)(smx + F_QL);
    __nv_bfloat16* KH = (__nv_bfloat16*)(smx + F_KH);
    __nv_bfloat16* KL = (__nv_bfloat16*)(smx + F_KL);
    __nv_bfloat16* VH = (__nv_bfloat16*)(smx + F_VH);
    __nv_bfloat16* VL = (__nv_bfloat16*)(smx + F_VL);
    float* PS = (float*)(smx + F_PS);
    __nv_bfloat16* PH = (__nv_bfloat16*)(smx + F_PH);
    __nv_bfloat16* PL = (__nv_bfloat16*)(smx + F_PL);
    float* OS   = (float*)(smx + F_OS);
    float* mrow = (float*)(smx + F_ST);
    float* lrow = mrow + 64;
    float* srow = lrow + 64;

    const int tid = threadIdx.x;
    const int w   = tid >> 5;
    const int qt  = blockIdx.x;
    const int h   = blockIdx.y;
    const int b   = blockIdx.z;
    const int q0  = qt * 64;
    const int kvh = h >> 2;
    const int m0  = (w >> 2) * 32;

#pragma unroll
    for (int t4 = 0; t4 < 4; t4++) {
        const int idx = tid + t4 * 256;
        const int r   = idx >> 4;
        const int c8  = (idx & 15) << 3;
        const size_t g = (((size_t)b * T_ + q0 + r) * H_ + h) * D_ + c8;
        *(uint4*)((char*)QH + r * (FQ_LD * 2) + c8 * 2) = *(const uint4*)(qh + g);
        *(uint4*)((char*)QL + r * (FQ_LD * 2) + c8 * 2) = *(const uint4*)(ql + g);
    }
    for (int idx = tid; idx < 64 * FO_LD; idx += 256) OS[idx] = 0.f;
    if (tid < 64) { mrow[tid] = -1e30f; lrow[tid] = 0.f; }
    __syncthreads();

    for (int kt = 0; kt <= qt; kt++) {
        const int k0 = kt * 64;
        const bool diag = (kt == qt);

#pragma unroll
        for (int t4 = 0; t4 < 4; t4++) {
            const int idx = tid + t4 * 256;
            const int r   = idx >> 4;
            const int c8  = (idx & 15) << 3;
            const size_t g = (((size_t)b * T_ + k0 + r) * KVH_ + kvh) * D_ + c8;
            const int so = r * (FQ_LD * 2) + c8 * 2;
            *(uint4*)((char*)KH + so) = *(const uint4*)(kh + g);
            *(uint4*)((char*)KL + so) = *(const uint4*)(kl + g);
            *(uint4*)((char*)VH + so) = *(const uint4*)(vh + g);
            *(uint4*)((char*)VL + so) = *(const uint4*)(vl + g);
        }
        __syncthreads();

        // ---- S = Q K^T (3-term)
        {
            const int n0 = (w & 3) * 16;
            wmma::fragment<wmma::accumulator, 16, 16, 16, float> sacc[2];
            wmma::fill_fragment(sacc[0], 0.f);
            wmma::fill_fragment(sacc[1], 0.f);
#pragma unroll
            for (int ks = 0; ks < 8; ks++) {
                wmma::fragment<wmma::matrix_b, 16, 16, 16, __nv_bfloat16,
                               wmma::col_major> fbh, fbl;
                wmma::load_matrix_sync(fbh, KH + n0 * FQ_LD + ks * 16, FQ_LD);
                wmma::load_matrix_sync(fbl, KL + n0 * FQ_LD + ks * 16, FQ_LD);
#pragma unroll
                for (int i = 0; i < 2; i++) {
                    wmma::fragment<wmma::matrix_a, 16, 16, 16, __nv_bfloat16,
                                   wmma::row_major> fah, fal;
                    wmma::load_matrix_sync(fah, QH + (m0 + i * 16) * FQ_LD + ks * 16, FQ_LD);
                    wmma::load_matrix_sync(fal, QL + (m0 + i * 16) * FQ_LD + ks * 16, FQ_LD);
                    wmma::mma_sync(sacc[i], fah, fbh, sacc[i]);
                    wmma::mma_sync(sacc[i], fah, fbl, sacc[i]);
                    wmma::mma_sync(sacc[i], fal, fbh, sacc[i]);
                }
            }
#pragma unroll
            for (int i = 0; i < 2; i++)
                wmma::store_matrix_sync(&PS[(m0 + i * 16) * FS_LD + n0],
                                        sacc[i], FS_LD, wmma::mem_row_major);
        }
        __syncthreads();

        // ---- pass 1: row max, 4 threads/row + shfl
        {
            const int r  = tid >> 2;
            const int l4 = tid & 3;
            const int cmax = diag ? r : 63;
            float mx = -1e30f;
            for (int c = l4; c <= cmax; c += 4)
                mx = fmaxf(mx, PS[r * FS_LD + c]);
            mx = fmaxf(mx, __shfl_xor_sync(0xffffffffu, mx, 1));
            mx = fmaxf(mx, __shfl_xor_sync(0xffffffffu, mx, 2));
            const float mold = mrow[r];
            const float mnew = fmaxf(mold, mx);
            if (l4 == 0) { mrow[r] = mnew; srow[r] = fast_exp(mold - mnew); }
        }
        __syncthreads();

        // ---- pass 2: exp (FMA pipe) + mask + P hi/lo split; O row rescale
        for (int idx = tid; idx < 4096; idx += 256) {
            const int r = idx >> 6, c = idx & 63;
            float p;
            if (diag && c > r) p = 0.f;
            else p = fast_exp(PS[r * FS_LD + c] - mrow[r]);
            PS[r * FS_LD + c] = p;
            const __nv_bfloat16 ph = __float2bfloat16(p);
            PH[r * FP_LD + c] = ph;
            PL[r * FP_LD + c] = __float2bfloat16(p - __bfloat162float(ph));
        }
        for (int idx = tid; idx < 8192; idx += 256) {
            const int r = idx >> 7, c = idx & 127;
            OS[r * FO_LD + c] *= srow[r];
        }
        __syncthreads();

        // ---- pass 3: row sums, 4 threads/row + shfl
        {
            const int r  = tid >> 2;
            const int l4 = tid & 3;
            float sum = 0.f;
            for (int c = l4; c < 64; c += 4) sum += PS[r * FS_LD + c];
            sum += __shfl_xor_sync(0xffffffffu, sum, 1);
            sum += __shfl_xor_sync(0xffffffffu, sum, 2);
            if (l4 == 0) lrow[r] = lrow[r] * srow[r] + sum;
        }

        // ---- O += P V (3-term)
        {
            const int d0 = (w & 3) * 32;
            wmma::fragment<wmma::accumulator, 16, 16, 16, float> oacc[2][2];
#pragma unroll
            for (int i = 0; i < 2; i++)
#pragma unroll
                for (int j = 0; j < 2; j++)
                    wmma::load_matrix_sync(oacc[i][j],
                        &OS[(m0 + i * 16) * FO_LD + d0 + j * 16],
                        FO_LD, wmma::mem_row_major);
#pragma unroll
            for (int ks = 0; ks < 4; ks++) {
                wmma::fragment<wmma::matrix_b, 16, 16, 16, __nv_bfloat16,
                               wmma::row_major> fvh[2], fvl[2];
#pragma unroll
                for (int j = 0; j < 2; j++) {
                    wmma::load_matrix_sync(fvh[j], VH + (ks * 16) * FQ_LD + d0 + j * 16, FQ_LD);
                    wmma::load_matrix_sync(fvl[j], VL + (ks * 16) * FQ_LD + d0 + j * 16, FQ_LD);
                }
#pragma unroll
                for (int i = 0; i < 2; i++) {
                    wmma::fragment<wmma::matrix_a, 16, 16, 16, __nv_bfloat16,
                                   wmma::row_major> fph, fpl;
                    wmma::load_matrix_sync(fph, PH + (m0 + i * 16) * FP_LD + ks * 16, FP_LD);
                    wmma::load_matrix_sync(fpl, PL + (m0 + i * 16) * FP_LD + ks * 16, FP_LD);
#pragma unroll
                    for (int j = 0; j < 2; j++) {
                        wmma::mma_sync(oacc[i][j], fph, fvh[j], oacc[i][j]);
                        wmma::mma_sync(oacc[i][j], fpl, fvh[j], oacc[i][j]);
                        wmma::mma_sync(oacc[i][j], fph, fvl[j], oacc[i][j]);
                    }
                }
            }
#pragma unroll
            for (int i = 0; i < 2; i++)
#pragma unroll
                for (int j = 0; j < 2; j++)
                    wmma::store_matrix_sync(
                        &OS[(m0 + i * 16) * FO_LD + d0 + j * 16],
                        oacc[i][j], FO_LD, wmma::mem_row_major);
        }
        __syncthreads();
    }

    for (int idx = tid; idx < 8192; idx += 256) {
        const int r = idx >> 7, c = idx & 127;
        const float o = OS[r * FO_LD + c] / lrow[r];
        const size_t g = (((size_t)b * T_ + q0 + r) * H_ + h) * D_ + c;
        __nv_bfloat16 oh16, ol16;
        split1(o, oh16, ol16);
        oh_out[g] = oh16;
        ol_out[g] = ol16;
    }
}

// ---------------------------------------------------------------------------
// Inputs (dict order, confirmed): 0 x, 1 start_pos, 2 inv_freqs, 3 mask,
// 4 Wq, 5 Wk, 6 Wv, 7 Wo, 8 bo. mask == hard causal; start_pos == 0.
// ---------------------------------------------------------------------------
extern "C" void kernel_launch(void* const* d_in, const int* in_sizes, int n_in,
                              void* d_out, int out_size)
{
    (void)in_sizes; (void)n_in; (void)out_size;
    const float* x   = (const float*)d_in[0];
    const float* inv = (const float*)d_in[2];
    const float* Wq  = (const float*)d_in[4];
    const float* Wk  = (const float*)d_in[5];
    const float* Wv  = (const float*)d_in[6];
    const float* Wo  = (const float*)d_in[7];
    const float* bo  = (const float*)d_in[8];
    float* out = (float*)d_out;

    __nv_bfloat16 *xh, *xl, *wqh, *wql, *wkh, *wkl, *wvh, *wvl, *woh, *wol;
    __nv_bfloat16 *ah, *al, *qh, *ql, *kh, *kl, *vh, *vl;
    cudaGetSymbolAddress((void**)&xh,  g_xh);  cudaGetSymbolAddress((void**)&xl,  g_xl);
    cudaGetSymbolAddress((void**)&wqh, g_wqh); cudaGetSymbolAddress((void**)&wql, g_wql);
    cudaGetSymbolAddress((void**)&wkh, g_wkh); cudaGetSymbolAddress((void**)&wkl, g_wkl);
    cudaGetSymbolAddress((void**)&wvh, g_wvh); cudaGetSymbolAddress((void**)&wvl, g_wvl);
    cudaGetSymbolAddress((void**)&woh, g_woh); cudaGetSymbolAddress((void**)&wol, g_wol);
    cudaGetSymbolAddress((void**)&ah,  g_ah);  cudaGetSymbolAddress((void**)&al,  g_al);
    cudaGetSymbolAddress((void**)&qh,  g_qh);  cudaGetSymbolAddress((void**)&ql,  g_ql);
    cudaGetSymbolAddress((void**)&kh,  g_kh);  cudaGetSymbolAddress((void**)&kl,  g_kl);
    cudaGetSymbolAddress((void**)&vh,  g_vh);  cudaGetSymbolAddress((void**)&vl,  g_vl);

    cudaFuncSetAttribute(gemm_qkv,
                         cudaFuncAttributeMaxDynamicSharedMemorySize, GEMM_SMEM);
    cudaFuncSetAttribute(gemm_bf16s,
                         cudaFuncAttributeMaxDynamicSharedMemorySize, GEMM_SMEM);
    cudaFuncSetAttribute(flash_tc,
                         cudaFuncAttributeMaxDynamicSharedMemorySize, FLASH_SMEM);

    const int M = B_ * T_;  // 8192

    split_all<<<NALL_ / 256, 256>>>(x, xh, xl, Wq, wqh, wql,
                                    Wk, wkh, wkl, Wv, wvh, wvl, Wo, woh, wol);

    gemm_qkv<<<dim3(24, M / 128), 256, GEMM_SMEM>>>(
        xh, xl, wqh, wql, wkh, wkl, wvh, wvl, inv,
        qh, ql, kh, kl, vh, vl);

    flash_tc<<<dim3(T_ / 64, H_, B_), 256, FLASH_SMEM>>>(
        qh, ql, kh, kl, vh, vl, ah, al);

    gemm_bf16s<<<dim3(C_ / 128, M / 128), 256, GEMM_SMEM>>>(
        ah, al, woh, wol, bo, out, M, C_, C_);
}

// round 16
// speedup vs baseline: 1.1642x; 1.1642x over previous
#include <cuda_runtime.h>
#include <cuda_bf16.h>
#include <mma.h>
#include <math.h>
#include <cstdint>

using namespace nvcuda;

#define B_    4
#define T_    2048
#define C_    2048
#define H_    16
#define KVH_  4
#define D_    128

// ---------------------------------------------------------------------------
// Scratch (device globals — no allocation allowed)
// ---------------------------------------------------------------------------
__device__ __nv_bfloat16 g_xh [B_ * T_ * C_];
__device__ __nv_bfloat16 g_xl [B_ * T_ * C_];
__device__ __nv_bfloat16 g_wqh[C_ * C_];
__device__ __nv_bfloat16 g_wql[C_ * C_];
__device__ __nv_bfloat16 g_wkh[KVH_ * D_ * C_];
__device__ __nv_bfloat16 g_wkl[KVH_ * D_ * C_];
__device__ __nv_bfloat16 g_wvh[KVH_ * D_ * C_];
__device__ __nv_bfloat16 g_wvl[KVH_ * D_ * C_];
__device__ __nv_bfloat16 g_woh[C_ * C_];
__device__ __nv_bfloat16 g_wol[C_ * C_];
__device__ __nv_bfloat16 g_ah [B_ * T_ * C_];   // flash O hi
__device__ __nv_bfloat16 g_al [B_ * T_ * C_];   // flash O lo
__device__ __nv_bfloat16 g_qh [B_ * T_ * H_   * D_];
__device__ __nv_bfloat16 g_ql [B_ * T_ * H_   * D_];
__device__ __nv_bfloat16 g_kh [B_ * T_ * KVH_ * D_];
__device__ __nv_bfloat16 g_kl [B_ * T_ * KVH_ * D_];
__device__ __nv_bfloat16 g_vh [B_ * T_ * KVH_ * D_];
__device__ __nv_bfloat16 g_vl [B_ * T_ * KVH_ * D_];

__device__ __forceinline__ uint32_t smem_u32(const void* p) {
    uint32_t a;
    asm("{ .reg .u64 t; cvta.to.shared.u64 t, %1; cvt.u32.u64 %0, t; }"
        : "=r"(a) : "l"(p));
    return a;
}
__device__ __forceinline__ void cp16(uint32_t saddr, const void* g) {
    asm volatile("cp.async.cg.shared.global [%0], [%1], 16;"
                 :: "r"(saddr), "l"(g) : "memory");
}
__device__ __forceinline__ void split1(float v, __nv_bfloat16& h, __nv_bfloat16& l) {
    h = __float2bfloat16(v);
    l = __float2bfloat16(v - __bfloat162float(h));
}

// FMA-pipe exp; x <= 0. Clamp BEFORE decomposition; exact 0 at x <= -88.
__device__ __forceinline__ float fast_exp(float x) {
    float y = x * 1.4426950408889634f;
    y = fmaxf(y, -127.0f);
    const float n = rintf(y);
    const float t = (y - n) * 0.6931471805599453f;
    float e = fmaf(t, 0.00833333333f, 0.0416666667f);
    e = fmaf(t, e, 0.16666666667f);
    e = fmaf(t, e, 0.5f);
    e = fmaf(t, e, 1.0f);
    e = fmaf(t, e, 1.0f);
    const float sc = __int_as_float(((int)n + 127) << 23);
    return e * sc;
}

// ---------------------------------------------------------------------------
// One-launch fp32 -> bf16 hi/lo split (x, Wq, Wk, Wv, Wo).
// ---------------------------------------------------------------------------
#define NX_  (B_ * T_ * C_)
#define NWQ_ (C_ * C_)
#define NWK_ (KVH_ * D_ * C_)
#define NALL_ (NX_ + 2 * NWQ_ + 2 * NWK_)

__global__ void split_all(
    const float* __restrict__ x,  __nv_bfloat16* __restrict__ xh,  __nv_bfloat16* __restrict__ xl,
    const float* __restrict__ wq, __nv_bfloat16* __restrict__ wqh, __nv_bfloat16* __restrict__ wql,
    const float* __restrict__ wk, __nv_bfloat16* __restrict__ wkh, __nv_bfloat16* __restrict__ wkl,
    const float* __restrict__ wv, __nv_bfloat16* __restrict__ wvh, __nv_bfloat16* __restrict__ wvl,
    const float* __restrict__ wo, __nv_bfloat16* __restrict__ woh, __nv_bfloat16* __restrict__ wol)
{
    long i = (long)blockIdx.x * blockDim.x + threadIdx.x;
    const float* s; __nv_bfloat16 *dh, *dl;
    if (i < NX_)                    { s = x;  dh = xh;  dl = xl; }
    else if ((i -= NX_)  < NWQ_)    { s = wq; dh = wqh; dl = wql; }
    else if ((i -= NWQ_) < NWK_)    { s = wk; dh = wkh; dl = wkl; }
    else if ((i -= NWK_) < NWK_)    { s = wv; dh = wvh; dl = wvl; }
    else if ((i -= NWK_) < NWQ_)    { s = wo; dh = woh; dl = wol; }
    else return;
    const float v = s[i];
    split1(v, dh[i], dl[i]);
}

// ---------------------------------------------------------------------------
// Shared GEMM config (R11-proven).
// ---------------------------------------------------------------------------
#define LDB        40
#define ARR_STRIDE (128 * LDB * 2)
#define STG_STRIDE (4 * ARR_STRIDE)
#define CS_LD      132
#define GEMM_SMEM  (2 * STG_STRIDE)

// ---------------------------------------------------------------------------
// Fused QKV GEMM + RoPE + scale + bf16 split (unchanged).
// ---------------------------------------------------------------------------
__global__ __launch_bounds__(256) void gemm_qkv(
    const __nv_bfloat16* __restrict__ xh,  const __nv_bfloat16* __restrict__ xl,
    const __nv_bfloat16* __restrict__ wqh, const __nv_bfloat16* __restrict__ wql,
    const __nv_bfloat16* __restrict__ wkh, const __nv_bfloat16* __restrict__ wkl,
    const __nv_bfloat16* __restrict__ wvh, const __nv_bfloat16* __restrict__ wvl,
    const float* __restrict__ inv,
    __nv_bfloat16* __restrict__ qh, __nv_bfloat16* __restrict__ ql,
    __nv_bfloat16* __restrict__ kh, __nv_bfloat16* __restrict__ kl,
    __nv_bfloat16* __restrict__ vh, __nv_bfloat16* __restrict__ vl)
{
    extern __shared__ char sm8[];
    const uint32_t sb = smem_u32(sm8);
    const int tid   = threadIdx.x;
    const int warp  = tid >> 5;
    const int warpM = warp >> 2;
    const int warpN = warp & 3;
    const int bm    = blockIdx.y * 128;
    const int bx    = blockIdx.x;
    const int K     = C_;

    const __nv_bfloat16 *Bh, *Bl;
    __nv_bfloat16 *dh, *dl;
    int bn, mode, nseg;
    if (bx < 16)      { Bh = wqh; Bl = wql; bn = bx * 128;        mode = 1; nseg = 2048; dh = qh; dl = ql; }
    else if (bx < 20) { Bh = wkh; Bl = wkl; bn = (bx - 16) * 128; mode = 2; nseg = 512;  dh = kh; dl = kl; }
    else              { Bh = wvh; Bl = wvl; bn = (bx - 20) * 128; mode = 3; nseg = 512;  dh = vh; dl = vl; }

    wmma::fragment<wmma::accumulator, 16, 16, 16, float> acc[4][2];
#pragma unroll
    for (int i = 0; i < 4; i++)
#pragma unroll
        for (int j = 0; j < 2; j++) wmma::fill_fragment(acc[i][j], 0.0f);

    auto stage_load = [&](int k0, int stg) {
#pragma unroll
        for (int t = 0; t < 2; t++) {
            const int idx = tid + t * 256;
            const int r   = idx >> 2;
            const int c8  = (idx & 3) << 3;
            const size_t ga = (size_t)(bm + r) * K + k0 + c8;
            const size_t gb = (size_t)(bn + r) * K + k0 + c8;
            const uint32_t so = sb + stg * STG_STRIDE + r * (LDB * 2) + c8 * 2;
            cp16(so,                  xh + ga);
            cp16(so + ARR_STRIDE,     xl + ga);
            cp16(so + 2 * ARR_STRIDE, Bh + gb);
            cp16(so + 3 * ARR_STRIDE, Bl + gb);
        }
        asm volatile("cp.async.commit_group;" ::: "memory");
    };

    stage_load(0, 0);

    for (int k0 = 0; k0 < K; k0 += 32) {
        const int stg = (k0 >> 5) & 1;
        if (k0 + 32 < K) {
            stage_load(k0 + 32, stg ^ 1);
            asm volatile("cp.async.wait_group 1;" ::: "memory");
        } else {
            asm volatile("cp.async.wait_group 0;" ::: "memory");
        }
        __syncthreads();

        const __nv_bfloat16* Ahs = (const __nv_bfloat16*)(sm8 + stg * STG_STRIDE);
        const __nv_bfloat16* Als = (const __nv_bfloat16*)(sm8 + stg * STG_STRIDE + ARR_STRIDE);
        const __nv_bfloat16* Bhs = (const __nv_bfloat16*)(sm8 + stg * STG_STRIDE + 2 * ARR_STRIDE);
        const __nv_bfloat16* Bls = (const __nv_bfloat16*)(sm8 + stg * STG_STRIDE + 3 * ARR_STRIDE);

#pragma unroll
        for (int ks = 0; ks < 2; ks++) {
            wmma::fragment<wmma::matrix_b, 16, 16, 16, __nv_bfloat16,
                           wmma::col_major> fbh[2], fbl[2];
#pragma unroll
            for (int j = 0; j < 2; j++) {
                wmma::load_matrix_sync(fbh[j], Bhs + (warpN * 32 + j * 16) * LDB + ks * 16, LDB);
                wmma::load_matrix_sync(fbl[j], Bls + (warpN * 32 + j * 16) * LDB + ks * 16, LDB);
            }
#pragma unroll
            for (int i = 0; i < 4; i++) {
                wmma::fragment<wmma::matrix_a, 16, 16, 16, __nv_bfloat16,
                               wmma::row_major> fah, fal;
                wmma::load_matrix_sync(fah, Ahs + (warpM * 64 + i * 16) * LDB + ks * 16, LDB);
                wmma::load_matrix_sync(fal, Als + (warpM * 64 + i * 16) * LDB + ks * 16, LDB);
#pragma unroll
                for (int j = 0; j < 2; j++) {
                    wmma::mma_sync(acc[i][j], fah, fbh[j], acc[i][j]);
                    wmma::mma_sync(acc[i][j], fah, fbl[j], acc[i][j]);
                    wmma::mma_sync(acc[i][j], fal, fbh[j], acc[i][j]);
                }
            }
        }
        __syncthreads();
    }

    float* Cs = (float*)sm8;
#pragma unroll
    for (int i = 0; i < 4; i++)
#pragma unroll
        for (int j = 0; j < 2; j++)
            wmma::store_matrix_sync(&Cs[(warpM * 64 + i * 16) * CS_LD + warpN * 32 + j * 16],
                                    acc[i][j], CS_LD, wmma::mem_row_major);
    __syncthreads();

    const float rscale = 0.08838834764831845f;
#pragma unroll
    for (int it = 0; it < 16; it++) {
        const int idx = tid + it * 256;
        const int r   = idx >> 5;
        const int c4  = (idx & 31) << 2;
        float4 v = *(float4*)&Cs[r * CS_LD + c4];

        const int m   = bm + r;
        const int t   = m & (T_ - 1);
        const int col = bn + c4;
        const int d   = col & 127;

        if (mode != 3) {
            float s0, c0, s1, c1;
            sincosf(inv[(size_t)t * D_ + d],     &s0, &c0);
            sincosf(inv[(size_t)t * D_ + d + 2], &s1, &c1);
            float y0 = v.x * c0 - v.y * s0;
            float y1 = v.y * c0 + v.x * s0;
            float y2 = v.z * c1 - v.w * s1;
            float y3 = v.w * c1 + v.z * s1;
            if (mode == 1) { y0 *= rscale; y1 *= rscale; y2 *= rscale; y3 *= rscale; }
            v.x = y0; v.y = y1; v.z = y2; v.w = y3;
        }

        __nv_bfloat16 h0, h1, h2, h3, l0, l1, l2, l3;
        split1(v.x, h0, l0); split1(v.y, h1, l1);
        split1(v.z, h2, l2); split1(v.w, h3, l3);

        uint2 PH, PL;
        PH.x = (uint32_t)__bfloat16_as_ushort(h0) | ((uint32_t)__bfloat16_as_ushort(h1) << 16);
        PH.y = (uint32_t)__bfloat16_as_ushort(h2) | ((uint32_t)__bfloat16_as_ushort(h3) << 16);
        PL.x = (uint32_t)__bfloat16_as_ushort(l0) | ((uint32_t)__bfloat16_as_ushort(l1) << 16);
        PL.y = (uint32_t)__bfloat16_as_ushort(l2) | ((uint32_t)__bfloat16_as_ushort(l3) << 16);
        const size_t g = (size_t)m * nseg + col;
        *(uint2*)(dh + g) = PH;
        *(uint2*)(dl + g) = PL;
    }
}

// ---------------------------------------------------------------------------
// Output GEMM (unchanged).
// ---------------------------------------------------------------------------
__global__ __launch_bounds__(256) void gemm_bf16s(
    const __nv_bfloat16* __restrict__ Ah, const __nv_bfloat16* __restrict__ Al,
    const __nv_bfloat16* __restrict__ Bh, const __nv_bfloat16* __restrict__ Bl,
    const float* __restrict__ bias, float* __restrict__ C,
    int M, int N, int K)
{
    extern __shared__ char sm8[];
    const uint32_t sb = smem_u32(sm8);
    const int tid   = threadIdx.x;
    const int warp  = tid >> 5;
    const int warpM = warp >> 2;
    const int warpN = warp & 3;
    const int bm    = blockIdx.y * 128;
    const int bn    = blockIdx.x * 128;

    wmma::fragment<wmma::accumulator, 16, 16, 16, float> acc[4][2];
#pragma unroll
    for (int i = 0; i < 4; i++)
#pragma unroll
        for (int j = 0; j < 2; j++) wmma::fill_fragment(acc[i][j], 0.0f);

    auto stage_load = [&](int k0, int stg) {
#pragma unroll
        for (int t = 0; t < 2; t++) {
            const int idx = tid + t * 256;
            const int r   = idx >> 2;
            const int c8  = (idx & 3) << 3;
            const size_t ga = (size_t)(bm + r) * K + k0 + c8;
            const size_t gb = (size_t)(bn + r) * K + k0 + c8;
            const uint32_t so = sb + stg * STG_STRIDE + r * (LDB * 2) + c8 * 2;
            cp16(so,                  Ah + ga);
            cp16(so + ARR_STRIDE,     Al + ga);
            cp16(so + 2 * ARR_STRIDE, Bh + gb);
            cp16(so + 3 * ARR_STRIDE, Bl + gb);
        }
        asm volatile("cp.async.commit_group;" ::: "memory");
    };

    stage_load(0, 0);

    for (int k0 = 0; k0 < K; k0 += 32) {
        const int stg = (k0 >> 5) & 1;
        if (k0 + 32 < K) {
            stage_load(k0 + 32, stg ^ 1);
            asm volatile("cp.async.wait_group 1;" ::: "memory");
        } else {
            asm volatile("cp.async.wait_group 0;" ::: "memory");
        }
        __syncthreads();

        const __nv_bfloat16* Ahs = (const __nv_bfloat16*)(sm8 + stg * STG_STRIDE);
        const __nv_bfloat16* Als = (const __nv_bfloat16*)(sm8 + stg * STG_STRIDE + ARR_STRIDE);
        const __nv_bfloat16* Bhs = (const __nv_bfloat16*)(sm8 + stg * STG_STRIDE + 2 * ARR_STRIDE);
        const __nv_bfloat16* Bls = (const __nv_bfloat16*)(sm8 + stg * STG_STRIDE + 3 * ARR_STRIDE);

#pragma unroll
        for (int ks = 0; ks < 2; ks++) {
            wmma::fragment<wmma::matrix_b, 16, 16, 16, __nv_bfloat16,
                           wmma::col_major> fbh[2], fbl[2];
#pragma unroll
            for (int j = 0; j < 2; j++) {
                wmma::load_matrix_sync(fbh[j], Bhs + (warpN * 32 + j * 16) * LDB + ks * 16, LDB);
                wmma::load_matrix_sync(fbl[j], Bls + (warpN * 32 + j * 16) * LDB + ks * 16, LDB);
            }
#pragma unroll
            for (int i = 0; i < 4; i++) {
                wmma::fragment<wmma::matrix_a, 16, 16, 16, __nv_bfloat16,
                               wmma::row_major> fah, fal;
                wmma::load_matrix_sync(fah, Ahs + (warpM * 64 + i * 16) * LDB + ks * 16, LDB);
                wmma::load_matrix_sync(fal, Als + (warpM * 64 + i * 16) * LDB + ks * 16, LDB);
#pragma unroll
                for (int j = 0; j < 2; j++) {
                    wmma::mma_sync(acc[i][j], fah, fbh[j], acc[i][j]);
                    wmma::mma_sync(acc[i][j], fah, fbl[j], acc[i][j]);
                    wmma::mma_sync(acc[i][j], fal, fbh[j], acc[i][j]);
                }
            }
        }
        __syncthreads();
    }

    float* Cs = (float*)sm8;
#pragma unroll
    for (int i = 0; i < 4; i++)
#pragma unroll
        for (int j = 0; j < 2; j++)
            wmma::store_matrix_sync(&Cs[(warpM * 64 + i * 16) * CS_LD + warpN * 32 + j * 16],
                                    acc[i][j], CS_LD, wmma::mem_row_major);
    __syncthreads();

#pragma unroll
    for (int it = 0; it < 16; it++) {
        const int idx = tid + it * 256;
        const int r   = idx >> 5;
        const int c4  = (idx & 31) << 2;
        float4 v = *(float4*)&Cs[r * CS_LD + c4];
        const float4 b = *(const float4*)(bias + bn + c4);
        v.x += b.x; v.y += b.y; v.z += b.z; v.w += b.w;
        *(float4*)(C + (size_t)(bm + r) * N + bn + c4) = v;
    }
}

// ---------------------------------------------------------------------------
// Tensor-core causal flash attention, restructured (R16):
//  - O accumulators resident in registers across all k-tiles
//  - scalar (tile-global) running max -> layout-free in-fragment rescale
//  - in-fragment exp before PS store (no separate max pass)
//  - cp.async double-buffered K/V (prefetch tile kt+1 during tile kt)
// ---------------------------------------------------------------------------
#define FQ_LD 136
#define FS_LD 68
#define FP_LD 72
#define KVT   17408                        // one 64x136 bf16 array
#define F_QH  0
#define F_QL  (F_QH + KVT)
#define F_KV0 (F_QL + KVT)                 // KH,KL,VH,VL at +0,+KVT,+2KVT,+3KVT
#define F_KV1 (F_KV0 + 4 * KVT)
#define F_PS  (F_KV1 + 4 * KVT)            // f32 64x68
#define F_PH  (F_PS + 64 * FS_LD * 4)
#define F_PL  (F_PH + 64 * FP_LD * 2)
#define F_ST  (F_PL + 64 * FP_LD * 2)
#define FLASH_SMEM (F_ST + 128 * 4)        // 210432 B

__global__ __launch_bounds__(256) void flash_tc(
    const __nv_bfloat16* __restrict__ qh, const __nv_bfloat16* __restrict__ ql,
    const __nv_bfloat16* __restrict__ kh, const __nv_bfloat16* __restrict__ kl,
    const __nv_bfloat16* __restrict__ vh, const __nv_bfloat16* __restrict__ vl,
    __nv_bfloat16* __restrict__ oh_out, __nv_bfloat16* __restrict__ ol_out)
{
    extern __shared__ char smx[];
    const uint32_t sb = smem_u32(smx);
    __nv_bfloat16* QH = (__nv_bfloat16*)(smx + F_QH);
    __nv_bfloat16* QL = (__nv_bfloat16*)(smx + F_QL);
    float* PS = (float*)(smx + F_PS);
    __nv_bfloat16* PH = (__nv_bfloat16*)(smx + F_PH);
    __nv_bfloat16* PL = (__nv_bfloat16*)(smx + F_PL);
    float* red  = (float*)(smx + F_ST);    // [8] warp maxes
    float* msl  = red + 8;                 // [2] running scalar max (parity)
    float* lrow = red + 16;                // [64] row sums

    const int tid = threadIdx.x;
    const int w   = tid >> 5;
    const int qt  = blockIdx.x;
    const int h   = blockIdx.y;
    const int b   = blockIdx.z;
    const int q0  = qt * 64;
    const int kvh = h >> 2;
    const int m0  = (w >> 2) * 32;
    const int n0  = (w & 3) * 16;
    const int d0  = (w & 3) * 32;

    // Prefetch K/V tile kt into buffer bu (cp.async; 16 chunks/thread)
    auto kv_issue = [&](int kt, int bu) {
        const int k0 = kt * 64;
#pragma unroll
        for (int t4 = 0; t4 < 4; t4++) {
            const int idx = tid + t4 * 256;
            const int r   = idx >> 4;
            const int c8  = (idx & 15) << 3;
            const size_t g = (((size_t)b * T_ + k0 + r) * KVH_ + kvh) * D_ + c8;
            const uint32_t so = sb + F_KV0 + bu * (4 * KVT) + r * (FQ_LD * 2) + c8 * 2;
            cp16(so,           kh + g);
            cp16(so + KVT,     kl + g);
            cp16(so + 2 * KVT, vh + g);
            cp16(so + 3 * KVT, vl + g);
        }
        asm volatile("cp.async.commit_group;" ::: "memory");
    };

    // Load Q (uint4 direct)
#pragma unroll
    for (int t4 = 0; t4 < 4; t4++) {
        const int idx = tid + t4 * 256;
        const int r   = idx >> 4;
        const int c8  = (idx & 15) << 3;
        const size_t g = (((size_t)b * T_ + q0 + r) * H_ + h) * D_ + c8;
        *(uint4*)((char*)QH + r * (FQ_LD * 2) + c8 * 2) = *(const uint4*)(qh + g);
        *(uint4*)((char*)QL + r * (FQ_LD * 2) + c8 * 2) = *(const uint4*)(ql + g);
    }
    if (tid < 64) lrow[tid] = 0.f;
    if (tid == 0) msl[0] = -1e30f;

    kv_issue(0, 0);

    // O accumulators resident in registers
    wmma::fragment<wmma::accumulator, 16, 16, 16, float> oacc[2][2];
#pragma unroll
    for (int i = 0; i < 2; i++)
#pragma unroll
        for (int j = 0; j < 2; j++) wmma::fill_fragment(oacc[i][j], 0.f);

    for (int kt = 0; kt <= qt; kt++) {
        const int bu = kt & 1;
        const bool diag = (kt == qt);
        if (kt < qt) {
            kv_issue(kt + 1, bu ^ 1);
            asm volatile("cp.async.wait_group 1;" ::: "memory");
        } else {
            asm volatile("cp.async.wait_group 0;" ::: "memory");
        }
        __syncthreads();                               // sync0: KV[bu] ready

        const __nv_bfloat16* KH = (const __nv_bfloat16*)(smx + F_KV0 + bu * (4 * KVT));
        const __nv_bfloat16* KL = KH + KVT / 2;
        const __nv_bfloat16* VH = KH + KVT;
        const __nv_bfloat16* VL = KH + 3 * (KVT / 2);

        // ---- S = Q K^T (3-term), frags stay in registers
        wmma::fragment<wmma::accumulator, 16, 16, 16, float> sacc[2];
        wmma::fill_fragment(sacc[0], 0.f);
        wmma::fill_fragment(sacc[1], 0.f);
#pragma unroll
        for (int ks = 0; ks < 8; ks++) {
            wmma::fragment<wmma::matrix_b, 16, 16, 16, __nv_bfloat16,
                           wmma::col_major> fbh, fbl;
            wmma::load_matrix_sync(fbh, KH + n0 * FQ_LD + ks * 16, FQ_LD);
            wmma::load_matrix_sync(fbl, KL + n0 * FQ_LD + ks * 16, FQ_LD);
#pragma unroll
            for (int i = 0; i < 2; i++) {
                wmma::fragment<wmma::matrix_a, 16, 16, 16, __nv_bfloat16,
                               wmma::row_major> fah, fal;
                wmma::load_matrix_sync(fah, QH + (m0 + i * 16) * FQ_LD + ks * 16, FQ_LD);
                wmma::load_matrix_sync(fal, QL + (m0 + i * 16) * FQ_LD + ks * 16, FQ_LD);
                wmma::mma_sync(sacc[i], fah, fbh, sacc[i]);
                wmma::mma_sync(sacc[i], fah, fbl, sacc[i]);
                wmma::mma_sync(sacc[i], fal, fbh, sacc[i]);
            }
        }

        // ---- warp max over fragments (layout-free), combine to scalar
        {
            float mx = -1e30f;
#pragma unroll
            for (int i = 0; i < 2; i++)
#pragma unroll
                for (int e = 0; e < sacc[0].num_elements; e++)
                    mx = fmaxf(mx, sacc[i].x[e]);
#pragma unroll
            for (int off = 16; off > 0; off >>= 1)
                mx = fmaxf(mx, __shfl_xor_sync(0xffffffffu, mx, off));
            if ((tid & 31) == 0) red[w] = mx;
        }
        __syncthreads();                               // sync1: red[] ready

        const float m_old = msl[kt & 1];
        float M = m_old;
#pragma unroll
        for (int i = 0; i < 8; i++) M = fmaxf(M, red[i]);
        const float s_scalar = fast_exp(m_old - M);
        if (tid == 0) msl[(kt + 1) & 1] = M;

        // ---- layout-free: rescale O accumulators; exp S in-fragment
#pragma unroll
        for (int i = 0; i < 2; i++)
#pragma unroll
            for (int j = 0; j < 2; j++)
#pragma unroll
                for (int e = 0; e < oacc[0][0].num_elements; e++)
                    oacc[i][j].x[e] *= s_scalar;
#pragma unroll
        for (int i = 0; i < 2; i++) {
#pragma unroll
            for (int e = 0; e < sacc[0].num_elements; e++)
                sacc[i].x[e] = fast_exp(sacc[i].x[e] - M);
            wmma::store_matrix_sync(&PS[(m0 + i * 16) * FS_LD + n0],
                                    sacc[i], FS_LD, wmma::mem_row_major);
        }
        __syncthreads();                               // sync2: PS ready

        // ---- split pass: mask + P hi/lo + row sums (4 threads/row)
        {
            const int r  = tid >> 2;
            const int l4 = tid & 3;
            float sum = 0.f;
#pragma unroll
            for (int cc = 0; cc < 16; cc++) {
                const int c = l4 + cc * 4;
                float p = PS[r * FS_LD + c];
                if (diag && c > r) p = 0.f;
                sum += p;
                __nv_bfloat16 ph16, pl16;
                split1(p, ph16, pl16);
                PH[r * FP_LD + c] = ph16;
                PL[r * FP_LD + c] = pl16;
            }
            sum += __shfl_xor_sync(0xffffffffu, sum, 1);
            sum += __shfl_xor_sync(0xffffffffu, sum, 2);
            if (l4 == 0) lrow[r] = lrow[r] * s_scalar + sum;
        }
        __syncthreads();                               // sync3: PH/PL ready

        // ---- O += P V (3-term) into register accumulators
#pragma unroll
        for (int ks = 0; ks < 4; ks++) {
            wmma::fragment<wmma::matrix_b, 16, 16, 16, __nv_bfloat16,
                           wmma::row_major> fvh[2], fvl[2];
#pragma unroll
            for (int j = 0; j < 2; j++) {
                wmma::load_matrix_sync(fvh[j], VH + (ks * 16) * FQ_LD + d0 + j * 16, FQ_LD);
                wmma::load_matrix_sync(fvl[j], VL + (ks * 16) * FQ_LD + d0 + j * 16, FQ_LD);
            }
#pragma unroll
            for (int i = 0; i < 2; i++) {
                wmma::fragment<wmma::matrix_a, 16, 16, 16, __nv_bfloat16,
                               wmma::row_major> fph, fpl;
                wmma::load_matrix_sync(fph, PH + (m0 + i * 16) * FP_LD + ks * 16, FP_LD);
                wmma::load_matrix_sync(fpl, PL + (m0 + i * 16) * FP_LD + ks * 16, FP_LD);
#pragma unroll
                for (int j = 0; j < 2; j++) {
                    wmma::mma_sync(oacc[i][j], fph, fvh[j], oacc[i][j]);
                    wmma::mma_sync(oacc[i][j], fpl, fvh[j], oacc[i][j]);
                    wmma::mma_sync(oacc[i][j], fph, fvl[j], oacc[i][j]);
                }
            }
        }
        __syncthreads();   // sync4: protect KV[bu] from the kt+2 prefetch
    }

    // Epilogue: O frags -> smem (reuse KV buffer 0), normalize, split out.
    float* OS = (float*)(smx + F_KV0);                 // 64 x 132 f32
#pragma unroll
    for (int i = 0; i < 2; i++)
#pragma unroll
        for (int j = 0; j < 2; j++)
            wmma::store_matrix_sync(&OS[(m0 + i * 16) * 132 + d0 + j * 16],
                                    oacc[i][j], 132, wmma::mem_row_major);
    __syncthreads();

    for (int idx = tid; idx < 8192; idx += 256) {
        const int r = idx >> 7, c = idx & 127;
        const float o = OS[r * 132 + c] / lrow[r];
        const size_t g = (((size_t)b * T_ + q0 + r) * H_ + h) * D_ + c;
        __nv_bfloat16 oh16, ol16;
        split1(o, oh16, ol16);
        oh_out[g] = oh16;
        ol_out[g] = ol16;
    }
}

// ---------------------------------------------------------------------------
// Inputs (dict order, confirmed): 0 x, 1 start_pos, 2 inv_freqs, 3 mask,
// 4 Wq, 5 Wk, 6 Wv, 7 Wo, 8 bo. mask == hard causal; start_pos == 0.
// ---------------------------------------------------------------------------
extern "C" void kernel_launch(void* const* d_in, const int* in_sizes, int n_in,
                              void* d_out, int out_size)
{
    (void)in_sizes; (void)n_in; (void)out_size;
    const float* x   = (const float*)d_in[0];
    const float* inv = (const float*)d_in[2];
    const float* Wq  = (const float*)d_in[4];
    const float* Wk  = (const float*)d_in[5];
    const float* Wv  = (const float*)d_in[6];
    const float* Wo  = (const float*)d_in[7];
    const float* bo  = (const float*)d_in[8];
    float* out = (float*)d_out;

    __nv_bfloat16 *xh, *xl, *wqh, *wql, *wkh, *wkl, *wvh, *wvl, *woh, *wol;
    __nv_bfloat16 *ah, *al, *qh, *ql, *kh, *kl, *vh, *vl;
    cudaGetSymbolAddress((void**)&xh,  g_xh);  cudaGetSymbolAddress((void**)&xl,  g_xl);
    cudaGetSymbolAddress((void**)&wqh, g_wqh); cudaGetSymbolAddress((void**)&wql, g_wql);
    cudaGetSymbolAddress((void**)&wkh, g_wkh); cudaGetSymbolAddress((void**)&wkl, g_wkl);
    cudaGetSymbolAddress((void**)&wvh, g_wvh); cudaGetSymbolAddress((void**)&wvl, g_wvl);
    cudaGetSymbolAddress((void**)&woh, g_woh); cudaGetSymbolAddress((void**)&wol, g_wol);
    cudaGetSymbolAddress((void**)&ah,  g_ah);  cudaGetSymbolAddress((void**)&al,  g_al);
    cudaGetSymbolAddress((void**)&qh,  g_qh);  cudaGetSymbolAddress((void**)&ql,  g_ql);
    cudaGetSymbolAddress((void**)&kh,  g_kh);  cudaGetSymbolAddress((void**)&kl,  g_kl);
    cudaGetSymbolAddress((void**)&vh,  g_vh);  cudaGetSymbolAddress((void**)&vl,  g_vl);

    cudaFuncSetAttribute(gemm_qkv,
                         cudaFuncAttributeMaxDynamicSharedMemorySize, GEMM_SMEM);
    cudaFuncSetAttribute(gemm_bf16s,
                         cudaFuncAttributeMaxDynamicSharedMemorySize, GEMM_SMEM);
    cudaFuncSetAttribute(flash_tc,
                         cudaFuncAttributeMaxDynamicSharedMemorySize, FLASH_SMEM);

    const int M = B_ * T_;  // 8192

    split_all<<<NALL_ / 256, 256>>>(x, xh, xl, Wq, wqh, wql,
                                    Wk, wkh, wkl, Wv, wvh, wvl, Wo, woh, wol);

    gemm_qkv<<<dim3(24, M / 128), 256, GEMM_SMEM>>>(
        xh, xl, wqh, wql, wkh, wkl, wvh, wvl, inv,
        qh, ql, kh, kl, vh, vl);

    flash_tc<<<dim3(T_ / 64, H_, B_), 256, FLASH_SMEM>>>(
        qh, ql, kh, kl, vh, vl, ah, al);

    gemm_bf16s<<<dim3(C_ / 128, M / 128), 256, GEMM_SMEM>>>(
        ah, al, woh, wol, bo, out, M, C_, C_);
}

// round 17
// speedup vs baseline: 1.1708x; 1.0057x over previous
#include <cuda_runtime.h>
#include <cuda_bf16.h>
#include <mma.h>
#include <math.h>
#include <cstdint>

using namespace nvcuda;

#define B_    4
#define T_    2048
#define C_    2048
#define H_    16
#define KVH_  4
#define D_    128

// ---------------------------------------------------------------------------
// Scratch (device globals — no allocation allowed)
// ---------------------------------------------------------------------------
__device__ __nv_bfloat16 g_xh [B_ * T_ * C_];
__device__ __nv_bfloat16 g_xl [B_ * T_ * C_];
__device__ __nv_bfloat16 g_wqh[C_ * C_];
__device__ __nv_bfloat16 g_wql[C_ * C_];
__device__ __nv_bfloat16 g_wkh[KVH_ * D_ * C_];
__device__ __nv_bfloat16 g_wkl[KVH_ * D_ * C_];
__device__ __nv_bfloat16 g_wvh[KVH_ * D_ * C_];
__device__ __nv_bfloat16 g_wvl[KVH_ * D_ * C_];
__device__ __nv_bfloat16 g_woh[C_ * C_];
__device__ __nv_bfloat16 g_wol[C_ * C_];
__device__ __nv_bfloat16 g_ah [B_ * T_ * C_];   // flash O hi
__device__ __nv_bfloat16 g_al [B_ * T_ * C_];   // flash O lo
__device__ __nv_bfloat16 g_qh [B_ * T_ * H_   * D_];
__device__ __nv_bfloat16 g_ql [B_ * T_ * H_   * D_];
__device__ __nv_bfloat16 g_kh [B_ * T_ * KVH_ * D_];
__device__ __nv_bfloat16 g_kl [B_ * T_ * KVH_ * D_];
__device__ __nv_bfloat16 g_vh [B_ * T_ * KVH_ * D_];
__device__ __nv_bfloat16 g_vl [B_ * T_ * KVH_ * D_];
__device__ float         g_ct [T_ * D_];        // cos(inv) table
__device__ float         g_st [T_ * D_];        // sin(inv) table

__device__ __forceinline__ uint32_t smem_u32(const void* p) {
    uint32_t a;
    asm("{ .reg .u64 t; cvta.to.shared.u64 t, %1; cvt.u32.u64 %0, t; }"
        : "=r"(a) : "l"(p));
    return a;
}
__device__ __forceinline__ void cp16(uint32_t saddr, const void* g) {
    asm volatile("cp.async.cg.shared.global [%0], [%1], 16;"
                 :: "r"(saddr), "l"(g) : "memory");
}
__device__ __forceinline__ void split1(float v, __nv_bfloat16& h, __nv_bfloat16& l) {
    h = __float2bfloat16(v);
    l = __float2bfloat16(v - __bfloat162float(h));
}

// FMA-pipe exp; x <= 0. Clamp BEFORE decomposition; exact 0 at x <= -88.
__device__ __forceinline__ float fast_exp(float x) {
    float y = x * 1.4426950408889634f;
    y = fmaxf(y, -127.0f);
    const float n = rintf(y);
    const float t = (y - n) * 0.6931471805599453f;
    float e = fmaf(t, 0.00833333333f, 0.0416666667f);
    e = fmaf(t, e, 0.16666666667f);
    e = fmaf(t, e, 0.5f);
    e = fmaf(t, e, 1.0f);
    e = fmaf(t, e, 1.0f);
    const float sc = __int_as_float(((int)n + 127) << 23);
    return e * sc;
}

// ---------------------------------------------------------------------------
// One-launch fp32 -> bf16 hi/lo split (x, Wq, Wk, Wv, Wo) + RoPE cos/sin
// table fill (removes slow accurate-sincosf from the gemm_qkv epilogue).
// ---------------------------------------------------------------------------
#define NX_  (B_ * T_ * C_)
#define NWQ_ (C_ * C_)
#define NWK_ (KVH_ * D_ * C_)
#define NT_  (T_ * D_)
#define NALL_ (NX_ + 2 * NWQ_ + 2 * NWK_ + NT_)

__global__ void split_all(
    const float* __restrict__ x,  __nv_bfloat16* __restrict__ xh,  __nv_bfloat16* __restrict__ xl,
    const float* __restrict__ wq, __nv_bfloat16* __restrict__ wqh, __nv_bfloat16* __restrict__ wql,
    const float* __restrict__ wk, __nv_bfloat16* __restrict__ wkh, __nv_bfloat16* __restrict__ wkl,
    const float* __restrict__ wv, __nv_bfloat16* __restrict__ wvh, __nv_bfloat16* __restrict__ wvl,
    const float* __restrict__ wo, __nv_bfloat16* __restrict__ woh, __nv_bfloat16* __restrict__ wol,
    const float* __restrict__ inv, float* __restrict__ ct, float* __restrict__ st)
{
    long i = (long)blockIdx.x * blockDim.x + threadIdx.x;
    const float* s; __nv_bfloat16 *dh, *dl;
    if (i < NX_)                    { s = x;  dh = xh;  dl = xl; }
    else if ((i -= NX_)  < NWQ_)    { s = wq; dh = wqh; dl = wql; }
    else if ((i -= NWQ_) < NWK_)    { s = wk; dh = wkh; dl = wkl; }
    else if ((i -= NWK_) < NWK_)    { s = wv; dh = wvh; dl = wvl; }
    else if ((i -= NWK_) < NWQ_)    { s = wo; dh = woh; dl = wol; }
    else if ((i -= NWQ_) < NT_) {
        float sv, cv;
        sincosf(inv[i], &sv, &cv);
        ct[i] = cv; st[i] = sv;
        return;
    }
    else return;
    const float v = s[i];
    split1(v, dh[i], dl[i]);
}

// ---------------------------------------------------------------------------
// Shared GEMM config (R11-proven).
// ---------------------------------------------------------------------------
#define LDB        40
#define ARR_STRIDE (128 * LDB * 2)
#define STG_STRIDE (4 * ARR_STRIDE)
#define CS_LD      132
#define GEMM_SMEM  (2 * STG_STRIDE)

// ---------------------------------------------------------------------------
// Fused QKV GEMM + RoPE (table-based) + scale + bf16 split.
// ---------------------------------------------------------------------------
__global__ __launch_bounds__(256) void gemm_qkv(
    const __nv_bfloat16* __restrict__ xh,  const __nv_bfloat16* __restrict__ xl,
    const __nv_bfloat16* __restrict__ wqh, const __nv_bfloat16* __restrict__ wql,
    const __nv_bfloat16* __restrict__ wkh, const __nv_bfloat16* __restrict__ wkl,
    const __nv_bfloat16* __restrict__ wvh, const __nv_bfloat16* __restrict__ wvl,
    const float* __restrict__ ct, const float* __restrict__ st,
    __nv_bfloat16* __restrict__ qh, __nv_bfloat16* __restrict__ ql,
    __nv_bfloat16* __restrict__ kh, __nv_bfloat16* __restrict__ kl,
    __nv_bfloat16* __restrict__ vh, __nv_bfloat16* __restrict__ vl)
{
    extern __shared__ char sm8[];
    const uint32_t sb = smem_u32(sm8);
    const int tid   = threadIdx.x;
    const int warp  = tid >> 5;
    const int warpM = warp >> 2;
    const int warpN = warp & 3;
    const int bm    = blockIdx.y * 128;
    const int bx    = blockIdx.x;
    const int K     = C_;

    const __nv_bfloat16 *Bh, *Bl;
    __nv_bfloat16 *dh, *dl;
    int bn, mode, nseg;
    if (bx < 16)      { Bh = wqh; Bl = wql; bn = bx * 128;        mode = 1; nseg = 2048; dh = qh; dl = ql; }
    else if (bx < 20) { Bh = wkh; Bl = wkl; bn = (bx - 16) * 128; mode = 2; nseg = 512;  dh = kh; dl = kl; }
    else              { Bh = wvh; Bl = wvl; bn = (bx - 20) * 128; mode = 3; nseg = 512;  dh = vh; dl = vl; }

    wmma::fragment<wmma::accumulator, 16, 16, 16, float> acc[4][2];
#pragma unroll
    for (int i = 0; i < 4; i++)
#pragma unroll
        for (int j = 0; j < 2; j++) wmma::fill_fragment(acc[i][j], 0.0f);

    auto stage_load = [&](int k0, int stg) {
#pragma unroll
        for (int t = 0; t < 2; t++) {
            const int idx = tid + t * 256;
            const int r   = idx >> 2;
            const int c8  = (idx & 3) << 3;
            const size_t ga = (size_t)(bm + r) * K + k0 + c8;
            const size_t gb = (size_t)(bn + r) * K + k0 + c8;
            const uint32_t so = sb + stg * STG_STRIDE + r * (LDB * 2) + c8 * 2;
            cp16(so,                  xh + ga);
            cp16(so + ARR_STRIDE,     xl + ga);
            cp16(so + 2 * ARR_STRIDE, Bh + gb);
            cp16(so + 3 * ARR_STRIDE, Bl + gb);
        }
        asm volatile("cp.async.commit_group;" ::: "memory");
    };

    stage_load(0, 0);

    for (int k0 = 0; k0 < K; k0 += 32) {
        const int stg = (k0 >> 5) & 1;
        if (k0 + 32 < K) {
            stage_load(k0 + 32, stg ^ 1);
            asm volatile("cp.async.wait_group 1;" ::: "memory");
        } else {
            asm volatile("cp.async.wait_group 0;" ::: "memory");
        }
        __syncthreads();

        const __nv_bfloat16* Ahs = (const __nv_bfloat16*)(sm8 + stg * STG_STRIDE);
        const __nv_bfloat16* Als = (const __nv_bfloat16*)(sm8 + stg * STG_STRIDE + ARR_STRIDE);
        const __nv_bfloat16* Bhs = (const __nv_bfloat16*)(sm8 + stg * STG_STRIDE + 2 * ARR_STRIDE);
        const __nv_bfloat16* Bls = (const __nv_bfloat16*)(sm8 + stg * STG_STRIDE + 3 * ARR_STRIDE);

#pragma unroll
        for (int ks = 0; ks < 2; ks++) {
            wmma::fragment<wmma::matrix_b, 16, 16, 16, __nv_bfloat16,
                           wmma::col_major> fbh[2], fbl[2];
#pragma unroll
            for (int j = 0; j < 2; j++) {
                wmma::load_matrix_sync(fbh[j], Bhs + (warpN * 32 + j * 16) * LDB + ks * 16, LDB);
                wmma::load_matrix_sync(fbl[j], Bls + (warpN * 32 + j * 16) * LDB + ks * 16, LDB);
            }
#pragma unroll
            for (int i = 0; i < 4; i++) {
                wmma::fragment<wmma::matrix_a, 16, 16, 16, __nv_bfloat16,
                               wmma::row_major> fah, fal;
                wmma::load_matrix_sync(fah, Ahs + (warpM * 64 + i * 16) * LDB + ks * 16, LDB);
                wmma::load_matrix_sync(fal, Als + (warpM * 64 + i * 16) * LDB + ks * 16, LDB);
#pragma unroll
                for (int j = 0; j < 2; j++) {
                    wmma::mma_sync(acc[i][j], fah, fbh[j], acc[i][j]);
                    wmma::mma_sync(acc[i][j], fah, fbl[j], acc[i][j]);
                    wmma::mma_sync(acc[i][j], fal, fbh[j], acc[i][j]);
                }
            }
        }
        __syncthreads();
    }

    float* Cs = (float*)sm8;
#pragma unroll
    for (int i = 0; i < 4; i++)
#pragma unroll
        for (int j = 0; j < 2; j++)
            wmma::store_matrix_sync(&Cs[(warpM * 64 + i * 16) * CS_LD + warpN * 32 + j * 16],
                                    acc[i][j], CS_LD, wmma::mem_row_major);
    __syncthreads();

    const float rscale = 0.08838834764831845f;
#pragma unroll
    for (int it = 0; it < 16; it++) {
        const int idx = tid + it * 256;
        const int r   = idx >> 5;
        const int c4  = (idx & 31) << 2;
        float4 v = *(float4*)&Cs[r * CS_LD + c4];

        const int m   = bm + r;
        const int t   = m & (T_ - 1);
        const int col = bn + c4;
        const int d   = col & 127;

        if (mode != 3) {
            const size_t ti = (size_t)t * D_ + d;
            const float c0 = ct[ti],     s0 = st[ti];
            const float c1 = ct[ti + 2], s1 = st[ti + 2];
            float y0 = v.x * c0 - v.y * s0;
            float y1 = v.y * c0 + v.x * s0;
            float y2 = v.z * c1 - v.w * s1;
            float y3 = v.w * c1 + v.z * s1;
            if (mode == 1) { y0 *= rscale; y1 *= rscale; y2 *= rscale; y3 *= rscale; }
            v.x = y0; v.y = y1; v.z = y2; v.w = y3;
        }

        __nv_bfloat16 h0, h1, h2, h3, l0, l1, l2, l3;
        split1(v.x, h0, l0); split1(v.y, h1, l1);
        split1(v.z, h2, l2); split1(v.w, h3, l3);

        uint2 PH, PL;
        PH.x = (uint32_t)__bfloat16_as_ushort(h0) | ((uint32_t)__bfloat16_as_ushort(h1) << 16);
        PH.y = (uint32_t)__bfloat16_as_ushort(h2) | ((uint32_t)__bfloat16_as_ushort(h3) << 16);
        PL.x = (uint32_t)__bfloat16_as_ushort(l0) | ((uint32_t)__bfloat16_as_ushort(l1) << 16);
        PL.y = (uint32_t)__bfloat16_as_ushort(l2) | ((uint32_t)__bfloat16_as_ushort(l3) << 16);
        const size_t g = (size_t)m * nseg + col;
        *(uint2*)(dh + g) = PH;
        *(uint2*)(dl + g) = PL;
    }
}

// ---------------------------------------------------------------------------
// Output GEMM (unchanged).
// ---------------------------------------------------------------------------
__global__ __launch_bounds__(256) void gemm_bf16s(
    const __nv_bfloat16* __restrict__ Ah, const __nv_bfloat16* __restrict__ Al,
    const __nv_bfloat16* __restrict__ Bh, const __nv_bfloat16* __restrict__ Bl,
    const float* __restrict__ bias, float* __restrict__ C,
    int M, int N, int K)
{
    extern __shared__ char sm8[];
    const uint32_t sb = smem_u32(sm8);
    const int tid   = threadIdx.x;
    const int warp  = tid >> 5;
    const int warpM = warp >> 2;
    const int warpN = warp & 3;
    const int bm    = blockIdx.y * 128;
    const int bn    = blockIdx.x * 128;

    wmma::fragment<wmma::accumulator, 16, 16, 16, float> acc[4][2];
#pragma unroll
    for (int i = 0; i < 4; i++)
#pragma unroll
        for (int j = 0; j < 2; j++) wmma::fill_fragment(acc[i][j], 0.0f);

    auto stage_load = [&](int k0, int stg) {
#pragma unroll
        for (int t = 0; t < 2; t++) {
            const int idx = tid + t * 256;
            const int r   = idx >> 2;
            const int c8  = (idx & 3) << 3;
            const size_t ga = (size_t)(bm + r) * K + k0 + c8;
            const size_t gb = (size_t)(bn + r) * K + k0 + c8;
            const uint32_t so = sb + stg * STG_STRIDE + r * (LDB * 2) + c8 * 2;
            cp16(so,                  Ah + ga);
            cp16(so + ARR_STRIDE,     Al + ga);
            cp16(so + 2 * ARR_STRIDE, Bh + gb);
            cp16(so + 3 * ARR_STRIDE, Bl + gb);
        }
        asm volatile("cp.async.commit_group;" ::: "memory");
    };

    stage_load(0, 0);

    for (int k0 = 0; k0 < K; k0 += 32) {
        const int stg = (k0 >> 5) & 1;
        if (k0 + 32 < K) {
            stage_load(k0 + 32, stg ^ 1);
            asm volatile("cp.async.wait_group 1;" ::: "memory");
        } else {
            asm volatile("cp.async.wait_group 0;" ::: "memory");
        }
        __syncthreads();

        const __nv_bfloat16* Ahs = (const __nv_bfloat16*)(sm8 + stg * STG_STRIDE);
        const __nv_bfloat16* Als = (const __nv_bfloat16*)(sm8 + stg * STG_STRIDE + ARR_STRIDE);
        const __nv_bfloat16* Bhs = (const __nv_bfloat16*)(sm8 + stg * STG_STRIDE + 2 * ARR_STRIDE);
        const __nv_bfloat16* Bls = (const __nv_bfloat16*)(sm8 + stg * STG_STRIDE + 3 * ARR_STRIDE);

#pragma unroll
        for (int ks = 0; ks < 2; ks++) {
            wmma::fragment<wmma::matrix_b, 16, 16, 16, __nv_bfloat16,
                           wmma::col_major> fbh[2], fbl[2];
#pragma unroll
            for (int j = 0; j < 2; j++) {
                wmma::load_matrix_sync(fbh[j], Bhs + (warpN * 32 + j * 16) * LDB + ks * 16, LDB);
                wmma::load_matrix_sync(fbl[j], Bls + (warpN * 32 + j * 16) * LDB + ks * 16, LDB);
            }
#pragma unroll
            for (int i = 0; i < 4; i++) {
                wmma::fragment<wmma::matrix_a, 16, 16, 16, __nv_bfloat16,
                               wmma::row_major> fah, fal;
                wmma::load_matrix_sync(fah, Ahs + (warpM * 64 + i * 16) * LDB + ks * 16, LDB);
                wmma::load_matrix_sync(fal, Als + (warpM * 64 + i * 16) * LDB + ks * 16, LDB);
#pragma unroll
                for (int j = 0; j < 2; j++) {
                    wmma::mma_sync(acc[i][j], fah, fbh[j], acc[i][j]);
                    wmma::mma_sync(acc[i][j], fah, fbl[j], acc[i][j]);
                    wmma::mma_sync(acc[i][j], fal, fbh[j], acc[i][j]);
                }
            }
        }
        __syncthreads();
    }

    float* Cs = (float*)sm8;
#pragma unroll
    for (int i = 0; i < 4; i++)
#pragma unroll
        for (int j = 0; j < 2; j++)
            wmma::store_matrix_sync(&Cs[(warpM * 64 + i * 16) * CS_LD + warpN * 32 + j * 16],
                                    acc[i][j], CS_LD, wmma::mem_row_major);
    __syncthreads();

#pragma unroll
    for (int it = 0; it < 16; it++) {
        const int idx = tid + it * 256;
        const int r   = idx >> 5;
        const int c4  = (idx & 31) << 2;
        float4 v = *(float4*)&Cs[r * CS_LD + c4];
        const float4 b = *(const float4*)(bias + bn + c4);
        v.x += b.x; v.y += b.y; v.z += b.z; v.w += b.w;
        *(float4*)(C + (size_t)(bm + r) * N + bn + c4) = v;
    }
}

// ---------------------------------------------------------------------------
// Tensor-core causal flash attention (R16, unchanged — committed baseline).
// ---------------------------------------------------------------------------
#define FQ_LD 136
#define FS_LD 68
#define FP_LD 72
#define KVT   17408
#define F_QH  0
#define F_QL  (F_QH + KVT)
#define F_KV0 (F_QL + KVT)
#define F_KV1 (F_KV0 + 4 * KVT)
#define F_PS  (F_KV1 + 4 * KVT)
#define F_PH  (F_PS + 64 * FS_LD * 4)
#define F_PL  (F_PH + 64 * FP_LD * 2)
#define F_ST  (F_PL + 64 * FP_LD * 2)
#define FLASH_SMEM (F_ST + 128 * 4)

__global__ __launch_bounds__(256) void flash_tc(
    const __nv_bfloat16* __restrict__ qh, const __nv_bfloat16* __restrict__ ql,
    const __nv_bfloat16* __restrict__ kh, const __nv_bfloat16* __restrict__ kl,
    const __nv_bfloat16* __restrict__ vh, const __nv_bfloat16* __restrict__ vl,
    __nv_bfloat16* __restrict__ oh_out, __nv_bfloat16* __restrict__ ol_out)
{
    extern __shared__ char smx[];
    const uint32_t sb = smem_u32(smx);
    __nv_bfloat16* QH = (__nv_bfloat16*)(smx + F_QH);
    __nv_bfloat16* QL = (__nv_bfloat16*)(smx + F_QL);
    float* PS = (float*)(smx + F_PS);
    __nv_bfloat16* PH = (__nv_bfloat16*)(smx + F_PH);
    __nv_bfloat16* PL = (__nv_bfloat16*)(smx + F_PL);
    float* red  = (float*)(smx + F_ST);
    float* msl  = red + 8;
    float* lrow = red + 16;

    const int tid = threadIdx.x;
    const int w   = tid >> 5;
    const int qt  = blockIdx.x;
    const int h   = blockIdx.y;
    const int b   = blockIdx.z;
    const int q0  = qt * 64;
    const int kvh = h >> 2;
    const int m0  = (w >> 2) * 32;
    const int n0  = (w & 3) * 16;
    const int d0  = (w & 3) * 32;

    auto kv_issue = [&](int kt, int bu) {
        const int k0 = kt * 64;
#pragma unroll
        for (int t4 = 0; t4 < 4; t4++) {
            const int idx = tid + t4 * 256;
            const int r   = idx >> 4;
            const int c8  = (idx & 15) << 3;
            const size_t g = (((size_t)b * T_ + k0 + r) * KVH_ + kvh) * D_ + c8;
            const uint32_t so = sb + F_KV0 + bu * (4 * KVT) + r * (FQ_LD * 2) + c8 * 2;
            cp16(so,           kh + g);
            cp16(so + KVT,     kl + g);
            cp16(so + 2 * KVT, vh + g);
            cp16(so + 3 * KVT, vl + g);
        }
        asm volatile("cp.async.commit_group;" ::: "memory");
    };

#pragma unroll
    for (int t4 = 0; t4 < 4; t4++) {
        const int idx = tid + t4 * 256;
        const int r   = idx >> 4;
        const int c8  = (idx & 15) << 3;
        const size_t g = (((size_t)b * T_ + q0 + r) * H_ + h) * D_ + c8;
        *(uint4*)((char*)QH + r * (FQ_LD * 2) + c8 * 2) = *(const uint4*)(qh + g);
        *(uint4*)((char*)QL + r * (FQ_LD * 2) + c8 * 2) = *(const uint4*)(ql + g);
    }
    if (tid < 64) lrow[tid] = 0.f;
    if (tid == 0) msl[0] = -1e30f;

    kv_issue(0, 0);

    wmma::fragment<wmma::accumulator, 16, 16, 16, float> oacc[2][2];
#pragma unroll
    for (int i = 0; i < 2; i++)
#pragma unroll
        for (int j = 0; j < 2; j++) wmma::fill_fragment(oacc[i][j], 0.f);

    for (int kt = 0; kt <= qt; kt++) {
        const int bu = kt & 1;
        const bool diag = (kt == qt);
        if (kt < qt) {
            kv_issue(kt + 1, bu ^ 1);
            asm volatile("cp.async.wait_group 1;" ::: "memory");
        } else {
            asm volatile("cp.async.wait_group 0;" ::: "memory");
        }
        __syncthreads();

        const __nv_bfloat16* KH = (const __nv_bfloat16*)(smx + F_KV0 + bu * (4 * KVT));
        const __nv_bfloat16* KL = KH + KVT / 2;
        const __nv_bfloat16* VH = KH + KVT;
        const __nv_bfloat16* VL = KH + 3 * (KVT / 2);

        wmma::fragment<wmma::accumulator, 16, 16, 16, float> sacc[2];
        wmma::fill_fragment(sacc[0], 0.f);
        wmma::fill_fragment(sacc[1], 0.f);
#pragma unroll
        for (int ks = 0; ks < 8; ks++) {
            wmma::fragment<wmma::matrix_b, 16, 16, 16, __nv_bfloat16,
                           wmma::col_major> fbh, fbl;
            wmma::load_matrix_sync(fbh, KH + n0 * FQ_LD + ks * 16, FQ_LD);
            wmma::load_matrix_sync(fbl, KL + n0 * FQ_LD + ks * 16, FQ_LD);
#pragma unroll
            for (int i = 0; i < 2; i++) {
                wmma::fragment<wmma::matrix_a, 16, 16, 16, __nv_bfloat16,
                               wmma::row_major> fah, fal;
                wmma::load_matrix_sync(fah, QH + (m0 + i * 16) * FQ_LD + ks * 16, FQ_LD);
                wmma::load_matrix_sync(fal, QL + (m0 + i * 16) * FQ_LD + ks * 16, FQ_LD);
                wmma::mma_sync(sacc[i], fah, fbh, sacc[i]);
                wmma::mma_sync(sacc[i], fah, fbl, sacc[i]);
                wmma::mma_sync(sacc[i], fal, fbh, sacc[i]);
            }
        }

        {
            float mx = -1e30f;
#pragma unroll
            for (int i = 0; i < 2; i++)
#pragma unroll
                for (int e = 0; e < sacc[0].num_elements; e++)
                    mx = fmaxf(mx, sacc[i].x[e]);
#pragma unroll
            for (int off = 16; off > 0; off >>= 1)
                mx = fmaxf(mx, __shfl_xor_sync(0xffffffffu, mx, off));
            if ((tid & 31) == 0) red[w] = mx;
        }
        __syncthreads();

        const float m_old = msl[kt & 1];
        float M = m_old;
#pragma unroll
        for (int i = 0; i < 8; i++) M = fmaxf(M, red[i]);
        const float s_scalar = fast_exp(m_old - M);
        if (tid == 0) msl[(kt + 1) & 1] = M;

#pragma unroll
        for (int i = 0; i < 2; i++)
#pragma unroll
            for (int j = 0; j < 2; j++)
#pragma unroll
                for (int e = 0; e < oacc[0][0].num_elements; e++)
                    oacc[i][j].x[e] *= s_scalar;
#pragma unroll
        for (int i = 0; i < 2; i++) {
#pragma unroll
            for (int e = 0; e < sacc[0].num_elements; e++)
                sacc[i].x[e] = fast_exp(sacc[i].x[e] - M);
            wmma::store_matrix_sync(&PS[(m0 + i * 16) * FS_LD + n0],
                                    sacc[i], FS_LD, wmma::mem_row_major);
        }
        __syncthreads();

        {
            const int r  = tid >> 2;
            const int l4 = tid & 3;
            float sum = 0.f;
#pragma unroll
            for (int cc = 0; cc < 16; cc++) {
                const int c = l4 + cc * 4;
                float p = PS[r * FS_LD + c];
                if (diag && c > r) p = 0.f;
                sum += p;
                __nv_bfloat16 ph16, pl16;
                split1(p, ph16, pl16);
                PH[r * FP_LD + c] = ph16;
                PL[r * FP_LD + c] = pl16;
            }
            sum += __shfl_xor_sync(0xffffffffu, sum, 1);
            sum += __shfl_xor_sync(0xffffffffu, sum, 2);
            if (l4 == 0) lrow[r] = lrow[r] * s_scalar + sum;
        }
        __syncthreads();

#pragma unroll
        for (int ks = 0; ks < 4; ks++) {
            wmma::fragment<wmma::matrix_b, 16, 16, 16, __nv_bfloat16,
                           wmma::row_major> fvh[2], fvl[2];
#pragma unroll
            for (int j = 0; j < 2; j++) {
                wmma::load_matrix_sync(fvh[j], VH + (ks * 16) * FQ_LD + d0 + j * 16, FQ_LD);
                wmma::load_matrix_sync(fvl[j], VL + (ks * 16) * FQ_LD + d0 + j * 16, FQ_LD);
            }
#pragma unroll
            for (int i = 0; i < 2; i++) {
                wmma::fragment<wmma::matrix_a, 16, 16, 16, __nv_bfloat16,
                               wmma::row_major> fph, fpl;
                wmma::load_matrix_sync(fph, PH + (m0 + i * 16) * FP_LD + ks * 16, FP_LD);
                wmma::load_matrix_sync(fpl, PL + (m0 + i * 16) * FP_LD + ks * 16, FP_LD);
#pragma unroll
                for (int j = 0; j < 2; j++) {
                    wmma::mma_sync(oacc[i][j], fph, fvh[j], oacc[i][j]);
                    wmma::mma_sync(oacc[i][j], fpl, fvh[j], oacc[i][j]);
                    wmma::mma_sync(oacc[i][j], fph, fvl[j], oacc[i][j]);
                }
            }
        }
        __syncthreads();
    }

    float* OS = (float*)(smx + F_KV0);
#pragma unroll
    for (int i = 0; i < 2; i++)
#pragma unroll
        for (int j = 0; j < 2; j++)
            wmma::store_matrix_sync(&OS[(m0 + i * 16) * 132 + d0 + j * 16],
                                    oacc[i][j], 132, wmma::mem_row_major);
    __syncthreads();

    for (int idx = tid; idx < 8192; idx += 256) {
        const int r = idx >> 7, c = idx & 127;
        const float o = OS[r * 132 + c] / lrow[r];
        const size_t g = (((size_t)b * T_ + q0 + r) * H_ + h) * D_ + c;
        __nv_bfloat16 oh16, ol16;
        split1(o, oh16, ol16);
        oh_out[g] = oh16;
        ol_out[g] = ol16;
    }
}

// ---------------------------------------------------------------------------
// Inputs (dict order, confirmed): 0 x, 1 start_pos, 2 inv_freqs, 3 mask,
// 4 Wq, 5 Wk, 6 Wv, 7 Wo, 8 bo. mask == hard causal; start_pos == 0.
// ---------------------------------------------------------------------------
extern "C" void kernel_launch(void* const* d_in, const int* in_sizes, int n_in,
                              void* d_out, int out_size)
{
    (void)in_sizes; (void)n_in; (void)out_size;
    const float* x   = (const float*)d_in[0];
    const float* inv = (const float*)d_in[2];
    const float* Wq  = (const float*)d_in[4];
    const float* Wk  = (const float*)d_in[5];
    const float* Wv  = (const float*)d_in[6];
    const float* Wo  = (const float*)d_in[7];
    const float* bo  = (const float*)d_in[8];
    float* out = (float*)d_out;

    __nv_bfloat16 *xh, *xl, *wqh, *wql, *wkh, *wkl, *wvh, *wvl, *woh, *wol;
    __nv_bfloat16 *ah, *al, *qh, *ql, *kh, *kl, *vh, *vl;
    float *ct, *st;
    cudaGetSymbolAddress((void**)&xh,  g_xh);  cudaGetSymbolAddress((void**)&xl,  g_xl);
    cudaGetSymbolAddress((void**)&wqh, g_wqh); cudaGetSymbolAddress((void**)&wql, g_wql);
    cudaGetSymbolAddress((void**)&wkh, g_wkh); cudaGetSymbolAddress((void**)&wkl, g_wkl);
    cudaGetSymbolAddress((void**)&wvh, g_wvh); cudaGetSymbolAddress((void**)&wvl, g_wvl);
    cudaGetSymbolAddress((void**)&woh, g_woh); cudaGetSymbolAddress((void**)&wol, g_wol);
    cudaGetSymbolAddress((void**)&ah,  g_ah);  cudaGetSymbolAddress((void**)&al,  g_al);
    cudaGetSymbolAddress((void**)&qh,  g_qh);  cudaGetSymbolAddress((void**)&ql,  g_ql);
    cudaGetSymbolAddress((void**)&kh,  g_kh);  cudaGetSymbolAddress((void**)&kl,  g_kl);
    cudaGetSymbolAddress((void**)&vh,  g_vh);  cudaGetSymbolAddress((void**)&vl,  g_vl);
    cudaGetSymbolAddress((void**)&ct,  g_ct);  cudaGetSymbolAddress((void**)&st,  g_st);

    cudaFuncSetAttribute(gemm_qkv,
                         cudaFuncAttributeMaxDynamicSharedMemorySize, GEMM_SMEM);
    cudaFuncSetAttribute(gemm_bf16s,
                         cudaFuncAttributeMaxDynamicSharedMemorySize, GEMM_SMEM);
    cudaFuncSetAttribute(flash_tc,
                         cudaFuncAttributeMaxDynamicSharedMemorySize, FLASH_SMEM);

    const int M = B_ * T_;  // 8192

    split_all<<<(NALL_ + 255) / 256, 256>>>(x, xh, xl, Wq, wqh, wql,
                                            Wk, wkh, wkl, Wv, wvh, wvl,
                                            Wo, woh, wol, inv, ct, st);

    gemm_qkv<<<dim3(24, M / 128), 256, GEMM_SMEM>>>(
        xh, xl, wqh, wql, wkh, wkl, wvh, wvl, ct, st,
        qh, ql, kh, kl, vh, vl);

    flash_tc<<<dim3(T_ / 64, H_, B_), 256, FLASH_SMEM>>>(
        qh, ql, kh, kl, vh, vl, ah, al);

    gemm_bf16s<<<dim3(C_ / 128, M / 128), 256, GEMM_SMEM>>>(
        ah, al, woh, wol, bo, out, M, C_, C_);
}